// round 3
// baseline (speedup 1.0000x reference)
#include <cuda_runtime.h>
#include <math.h>

// ---------------------------------------------------------------------------
// fs_net_loss — single fused kernel.
// Phase 1 (all 2048 blocks): streaming float4 L1 over 2x 50MB recon tensors,
//   per-block partial -> device scratch.
// Phase 2 (last block to arrive, via atomic counter): tail-reduce 2048
//   partials + tiny rot1/rot2/tran/size losses + write out[5] + reset counter.
// Deterministic: tree reductions only, counter self-resets each launch.
// No inter-block waiting -> no deadlock regardless of residency.
// ---------------------------------------------------------------------------

#define BS 128
#define N_PTS 32768
#define RECON_ELEMS (BS * N_PTS * 3)          // 12,582,912
#define RECON_V4   (RECON_ELEMS / 4)          // 3,145,728
#define NBLK 2048
#define NTHR 256
#define ITERS (RECON_V4 / (NBLK * NTHR))      // exactly 6
#define BASE 12

__device__ float        g_recon_partial[NBLK];
__device__ unsigned int g_counter = 0;

// cos/sin of 2*pi*k/12, k = 0..11
__device__ __constant__ float c_cos[BASE] = {
    1.0f,  0.8660254037844387f,  0.5f,  0.0f, -0.5f, -0.8660254037844387f,
   -1.0f, -0.8660254037844387f, -0.5f,  0.0f,  0.5f,  0.8660254037844387f };
__device__ __constant__ float c_sin[BASE] = {
    0.0f,  0.5f,  0.8660254037844387f,  1.0f,  0.8660254037844387f,  0.5f,
    0.0f, -0.5f, -0.8660254037844387f, -1.0f, -0.8660254037844387f, -0.5f };

__global__ __launch_bounds__(NTHR) void fsnet_fused_kernel(
    const float4* __restrict__ a,    // pred_Recon as float4
    const float4* __restrict__ bb,   // gt_Recon as float4
    const float* __restrict__ pR1,   // [BS,3]
    const float* __restrict__ pR2,   // [BS,3]
    const float* __restrict__ pT,    // [BS,3]
    const float* __restrict__ pS,    // [BS,3]
    const float* __restrict__ gR,    // [BS,3,3]
    const float* __restrict__ gT,    // [BS,3]
    const float* __restrict__ gS,    // [BS,3]
    const int*   __restrict__ sym,   // [BS,6]
    float* __restrict__ out)         // [5]
{
    const int tid = threadIdx.x;

    // ---------------- Phase 1: recon L1 partial ----------------
    const int base = blockIdx.x * NTHR + tid;
    float s = 0.0f;
    #pragma unroll
    for (int j = 0; j < ITERS; j++) {
        const int i = base + j * (NBLK * NTHR);
        const float4 x = a[i];
        const float4 y = bb[i];
        s += fabsf(x.x - y.x) + fabsf(x.y - y.y) +
             fabsf(x.z - y.z) + fabsf(x.w - y.w);
    }
    // warp reduce
    #pragma unroll
    for (int off = 16; off > 0; off >>= 1)
        s += __shfl_down_sync(0xffffffffu, s, off);
    __shared__ float warp_s[NTHR / 32];
    if ((tid & 31) == 0) warp_s[tid >> 5] = s;
    __syncthreads();
    __shared__ bool is_last;
    if (tid == 0) {
        float bs = 0.0f;
        #pragma unroll
        for (int w = 0; w < NTHR / 32; w++) bs += warp_s[w];
        g_recon_partial[blockIdx.x] = bs;
        __threadfence();
        unsigned int v = atomicAdd(&g_counter, 1u);
        is_last = (v == (unsigned int)(NBLK - 1));
    }
    __syncthreads();
    if (!is_last) return;

    // ---------------- Phase 2: last block does the tail ----------------
    float rsum = 0.0f;
    #pragma unroll
    for (int i = tid; i < NBLK; i += NTHR) rsum += g_recon_partial[i];
    __shared__ float rshare[NTHR];
    rshare[tid] = rsum;
    __syncthreads();

    __shared__ float sm[6][BS];
    if (tid < BS) {
        const int b = tid;
        const float* R = gR + b * 9;
        const float r00 = R[0], r01 = R[1], r02 = R[2];
        const float r10 = R[3], r11 = R[4], r12 = R[5];
        const float r20 = R[6], r21 = R[7], r22 = R[8];

        // rot1: +/- column 1 of R
        const float p0 = pR1[b*3+0], p1 = pR1[b*3+1], p2 = pR1[b*3+2];
        const float l1a = (fabsf(p0 - r01) + fabsf(p1 - r11) + fabsf(p2 - r21)) * (1.0f/3.0f);
        const float l1b = (fabsf(p0 + r01) + fabsf(p1 + r11) + fabsf(p2 + r21)) * (1.0f/3.0f);
        const float rot1 = (sym[b*6+2] == 1) ? fminf(l1a, l1b) : l1a;

        // rot2: cos(th_k)*col0(R) - sin(th_k)*col2(R)
        const float q0 = pR2[b*3+0], q1 = pR2[b*3+1], q2 = pR2[b*3+2];
        float best = 3.402823466e38f;
        #pragma unroll
        for (int k = 0; k < BASE; k++) {
            const float ck = c_cos[k], sk = c_sin[k];
            const float w0 = ck * r00 - sk * r02;
            const float w1 = ck * r10 - sk * r12;
            const float w2 = ck * r20 - sk * r22;
            const float l = (fabsf(q0 - w0) + fabsf(q1 - w1) + fabsf(q2 - w2)) * (1.0f/3.0f);
            best = fminf(best, l);
        }
        const float maskf = (sym[b*6+0] == 0) ? 1.0f : 0.0f;

        const float tr = fabsf(pT[b*3+0] - gT[b*3+0]) +
                         fabsf(pT[b*3+1] - gT[b*3+1]) +
                         fabsf(pT[b*3+2] - gT[b*3+2]);
        const float sz = fabsf(pS[b*3+0] - gS[b*3+0]) +
                         fabsf(pS[b*3+1] - gS[b*3+1]) +
                         fabsf(pS[b*3+2] - gS[b*3+2]);

        sm[0][b] = rot1;
        sm[1][b] = best * maskf;
        sm[2][b] = maskf;
        sm[3][b] = tr;
        sm[4][b] = sz;
        sm[5][b] = rshare[b] + rshare[b + BS];
    }
    __syncthreads();
    #pragma unroll
    for (int off = BS / 2; off > 0; off >>= 1) {
        if (tid < off) {
            #pragma unroll
            for (int j = 0; j < 6; j++) sm[j][tid] += sm[j][tid + off];
        }
        __syncthreads();
    }

    if (tid == 0) {
        const float valid = sm[2][0];
        out[0] = 8.0f * sm[0][0] * (1.0f / (float)BS);
        out[1] = 8.0f * ((valid > 0.0f) ? sm[1][0] / fmaxf(valid, 1.0f) : 0.0f);
        out[2] = 8.0f * sm[5][0] * (1.0f / (float)RECON_ELEMS);
        out[3] = 8.0f * sm[3][0] * (1.0f / (float)(BS * 3));
        out[4] = 8.0f * sm[4][0] * (1.0f / (float)(BS * 3));
        g_counter = 0u;   // reset for next graph replay
    }
}

extern "C" void kernel_launch(void* const* d_in, const int* in_sizes, int n_in,
                              void* d_out, int out_size)
{
    const float* pR1  = (const float*)d_in[0];
    const float* pR2  = (const float*)d_in[1];
    const float* pRec = (const float*)d_in[2];
    const float* pT   = (const float*)d_in[3];
    const float* pS   = (const float*)d_in[4];
    const float* gR   = (const float*)d_in[5];
    const float* gRec = (const float*)d_in[6];
    const float* gT   = (const float*)d_in[7];
    const float* gS   = (const float*)d_in[8];
    const int*   sym  = (const int*)d_in[9];
    float* out = (float*)d_out;

    fsnet_fused_kernel<<<NBLK, NTHR>>>((const float4*)pRec, (const float4*)gRec,
                                       pR1, pR2, pT, pS, gR, gT, gS, sym, out);
}

// round 4
// speedup vs baseline: 1.2144x; 1.2144x over previous
#include <cuda_runtime.h>
#include <math.h>

// ---------------------------------------------------------------------------
// fs_net_loss — single fused kernel, single-wave persistent grid.
// Phase 1: 592 blocks (148 SMs x 4) x 256 thr stream 2x 50MB recon tensors
//   with manual 4-way batched float4 loads (MLP=8/thread, 4 accumulators).
// Phase 2: last block to arrive (atomic counter) reduces partials + computes
//   rot1/rot2/tran/size + writes out[5] + resets counter.
// ---------------------------------------------------------------------------

#define BS 128
#define N_PTS 32768
#define RECON_ELEMS (BS * N_PTS * 3)          // 12,582,912
#define RECON_V4   (RECON_ELEMS / 4)          // 3,145,728
#define NBLK 592                               // 148 SMs x 4 blocks -> one wave
#define NTHR 256
#define STRIDE (NBLK * NTHR)                   // 151,552
#define BASE 12

__device__ float        g_recon_partial[NBLK];
__device__ unsigned int g_counter = 0;

__device__ __constant__ float c_cos[BASE] = {
    1.0f,  0.8660254037844387f,  0.5f,  0.0f, -0.5f, -0.8660254037844387f,
   -1.0f, -0.8660254037844387f, -0.5f,  0.0f,  0.5f,  0.8660254037844387f };
__device__ __constant__ float c_sin[BASE] = {
    0.0f,  0.5f,  0.8660254037844387f,  1.0f,  0.8660254037844387f,  0.5f,
    0.0f, -0.5f, -0.8660254037844387f, -1.0f, -0.8660254037844387f, -0.5f };

__device__ __forceinline__ float l1v4(const float4 x, const float4 y) {
    return fabsf(x.x - y.x) + fabsf(x.y - y.y) +
           fabsf(x.z - y.z) + fabsf(x.w - y.w);
}

__global__ __launch_bounds__(NTHR, 4) void fsnet_fused_kernel(
    const float4* __restrict__ a,    // pred_Recon as float4
    const float4* __restrict__ bb,   // gt_Recon as float4
    const float* __restrict__ pR1,   // [BS,3]
    const float* __restrict__ pR2,   // [BS,3]
    const float* __restrict__ pT,    // [BS,3]
    const float* __restrict__ pS,    // [BS,3]
    const float* __restrict__ gR,    // [BS,3,3]
    const float* __restrict__ gT,    // [BS,3]
    const float* __restrict__ gS,    // [BS,3]
    const int*   __restrict__ sym,   // [BS,6]
    float* __restrict__ out)         // [5]
{
    const int tid = threadIdx.x;

    // ---------------- Phase 1: recon L1 partial, 4-way batched ----------------
    float s0 = 0.0f, s1 = 0.0f, s2 = 0.0f, s3 = 0.0f;
    int i = blockIdx.x * NTHR + tid;
    for (; i + 3 * STRIDE < RECON_V4; i += 4 * STRIDE) {
        // 8 independent LDG.128 issued before any accumulation
        const float4 xa0 = a[i];
        const float4 xb0 = bb[i];
        const float4 xa1 = a[i + STRIDE];
        const float4 xb1 = bb[i + STRIDE];
        const float4 xa2 = a[i + 2 * STRIDE];
        const float4 xb2 = bb[i + 2 * STRIDE];
        const float4 xa3 = a[i + 3 * STRIDE];
        const float4 xb3 = bb[i + 3 * STRIDE];
        s0 += l1v4(xa0, xb0);
        s1 += l1v4(xa1, xb1);
        s2 += l1v4(xa2, xb2);
        s3 += l1v4(xa3, xb3);
    }
    for (; i < RECON_V4; i += STRIDE)
        s0 += l1v4(a[i], bb[i]);
    float s = (s0 + s1) + (s2 + s3);

    // warp reduce
    #pragma unroll
    for (int off = 16; off > 0; off >>= 1)
        s += __shfl_down_sync(0xffffffffu, s, off);
    __shared__ float warp_s[NTHR / 32];
    if ((tid & 31) == 0) warp_s[tid >> 5] = s;
    __syncthreads();
    __shared__ bool is_last;
    if (tid == 0) {
        float bsum = 0.0f;
        #pragma unroll
        for (int w = 0; w < NTHR / 32; w++) bsum += warp_s[w];
        g_recon_partial[blockIdx.x] = bsum;
        __threadfence();
        unsigned int v = atomicAdd(&g_counter, 1u);
        is_last = (v == (unsigned int)(NBLK - 1));
    }
    __syncthreads();
    if (!is_last) return;

    // ---------------- Phase 2: last block does the tail ----------------
    float rsum = 0.0f;
    for (int k = tid; k < NBLK; k += NTHR) rsum += g_recon_partial[k];
    __shared__ float rshare[NTHR];
    rshare[tid] = rsum;
    __syncthreads();

    __shared__ float sm[6][BS];
    if (tid < BS) {
        const int b = tid;
        const float* R = gR + b * 9;
        const float r00 = R[0], r01 = R[1], r02 = R[2];
        const float r10 = R[3], r11 = R[4], r12 = R[5];
        const float r20 = R[6], r21 = R[7], r22 = R[8];

        // rot1: +/- column 1 of R
        const float p0 = pR1[b*3+0], p1 = pR1[b*3+1], p2 = pR1[b*3+2];
        const float l1a = (fabsf(p0 - r01) + fabsf(p1 - r11) + fabsf(p2 - r21)) * (1.0f/3.0f);
        const float l1b = (fabsf(p0 + r01) + fabsf(p1 + r11) + fabsf(p2 + r21)) * (1.0f/3.0f);
        const float rot1 = (sym[b*6+2] == 1) ? fminf(l1a, l1b) : l1a;

        // rot2: cos(th_k)*col0(R) - sin(th_k)*col2(R)
        const float q0 = pR2[b*3+0], q1 = pR2[b*3+1], q2 = pR2[b*3+2];
        float best = 3.402823466e38f;
        #pragma unroll
        for (int k = 0; k < BASE; k++) {
            const float ck = c_cos[k], sk = c_sin[k];
            const float w0 = ck * r00 - sk * r02;
            const float w1 = ck * r10 - sk * r12;
            const float w2 = ck * r20 - sk * r22;
            const float l = (fabsf(q0 - w0) + fabsf(q1 - w1) + fabsf(q2 - w2)) * (1.0f/3.0f);
            best = fminf(best, l);
        }
        const float maskf = (sym[b*6+0] == 0) ? 1.0f : 0.0f;

        const float tr = fabsf(pT[b*3+0] - gT[b*3+0]) +
                         fabsf(pT[b*3+1] - gT[b*3+1]) +
                         fabsf(pT[b*3+2] - gT[b*3+2]);
        const float sz = fabsf(pS[b*3+0] - gS[b*3+0]) +
                         fabsf(pS[b*3+1] - gS[b*3+1]) +
                         fabsf(pS[b*3+2] - gS[b*3+2]);

        sm[0][b] = rot1;
        sm[1][b] = best * maskf;
        sm[2][b] = maskf;
        sm[3][b] = tr;
        sm[4][b] = sz;
        sm[5][b] = rshare[b] + rshare[b + BS];
    }
    __syncthreads();
    #pragma unroll
    for (int off = BS / 2; off > 0; off >>= 1) {
        if (tid < off) {
            #pragma unroll
            for (int j = 0; j < 6; j++) sm[j][tid] += sm[j][tid + off];
        }
        __syncthreads();
    }

    if (tid == 0) {
        const float valid = sm[2][0];
        out[0] = 8.0f * sm[0][0] * (1.0f / (float)BS);
        out[1] = 8.0f * ((valid > 0.0f) ? sm[1][0] / fmaxf(valid, 1.0f) : 0.0f);
        out[2] = 8.0f * sm[5][0] * (1.0f / (float)RECON_ELEMS);
        out[3] = 8.0f * sm[3][0] * (1.0f / (float)(BS * 3));
        out[4] = 8.0f * sm[4][0] * (1.0f / (float)(BS * 3));
        g_counter = 0u;   // reset for next graph replay
    }
}

extern "C" void kernel_launch(void* const* d_in, const int* in_sizes, int n_in,
                              void* d_out, int out_size)
{
    const float* pR1  = (const float*)d_in[0];
    const float* pR2  = (const float*)d_in[1];
    const float* pRec = (const float*)d_in[2];
    const float* pT   = (const float*)d_in[3];
    const float* pS   = (const float*)d_in[4];
    const float* gR   = (const float*)d_in[5];
    const float* gRec = (const float*)d_in[6];
    const float* gT   = (const float*)d_in[7];
    const float* gS   = (const float*)d_in[8];
    const int*   sym  = (const int*)d_in[9];
    float* out = (float*)d_out;

    fsnet_fused_kernel<<<NBLK, NTHR>>>((const float4*)pRec, (const float4*)gRec,
                                       pR1, pR2, pT, pS, gR, gT, gS, sym, out);
}